// round 17
// baseline (speedup 1.0000x reference)
#include <cuda_runtime.h>
#include <cfloat>
#include <cstdint>

#define NN 204800
#define EE 1638400
#define BB 4096
#define KK 10
#define HH 64
#define FIN 128
#define FEATW 192

// ---------------- scratch ----------------------------------------------------
__device__ int   g_cnt[NN];
__device__ int   g_bsum[800];
__device__ int   g_boff[800];
__device__ int   g_rowptr[NN + 1];
__device__ int   g_cursor[NN];
__device__ __align__(16) int2  g_es[EE];        // CSR slot -> {src, dst}
__device__ __align__(16) float g_ecoef[EE];     // CSR slot -> norm coef
__device__ __align__(16) float g_tmp[NN * HH];  // GEMM output h
__device__ __align__(16) float g_agg[NN * HH];  // init = h/(cnt+1), then RED
__device__ __align__(16) float g_feat[NN * FEATW];
__device__ float g_rowmax[NN];

// ---------------- degree / CSR build ------------------------------------------
__global__ void k_count(const int* __restrict__ ei) {
    int e = blockIdx.x * blockDim.x + threadIdx.x;
    if (e < EE) atomicAdd(&g_cnt[ei[EE + e]], 1);
}
__global__ void k_scan1() {
    __shared__ int s[256];
    int i = blockIdx.x * 256 + threadIdx.x;
    s[threadIdx.x] = g_cnt[i];
    __syncthreads();
    for (int o = 128; o; o >>= 1) {
        if (threadIdx.x < o) s[threadIdx.x] += s[threadIdx.x + o];
        __syncthreads();
    }
    if (threadIdx.x == 0) g_bsum[blockIdx.x] = s[0];
}
__global__ void k_scan2() {
    __shared__ int s[1024];
    int t = threadIdx.x;
    int v = (t < 800) ? g_bsum[t] : 0;
    s[t] = v;
    __syncthreads();
    for (int o = 1; o < 1024; o <<= 1) {
        int add = (t >= o) ? s[t - o] : 0;
        __syncthreads();
        s[t] += add;
        __syncthreads();
    }
    if (t < 800) g_boff[t] = s[t] - v;
}
__global__ void k_scan3() {
    __shared__ int s[256];
    int t = threadIdx.x;
    int i = blockIdx.x * 256 + t;
    int v = g_cnt[i];
    s[t] = v;
    __syncthreads();
    for (int o = 1; o < 256; o <<= 1) {
        int add = (t >= o) ? s[t - o] : 0;
        __syncthreads();
        s[t] += add;
        __syncthreads();
    }
    int rp = g_boff[blockIdx.x] + s[t] - v;
    g_rowptr[i] = rp;
    g_cursor[i] = rp;
    if (blockIdx.x == 799 && t == 255) g_rowptr[NN] = g_boff[799] + s[255];
}
__global__ void k_fill(const int* __restrict__ ei) {
    int e = blockIdx.x * blockDim.x + threadIdx.x;
    if (e >= EE) return;
    int r = ei[e];
    int c = ei[EE + e];
    int pos = atomicAdd(&g_cursor[c], 1);
    g_es[pos] = make_int2(r, c);
    int prod = (__ldg(&g_cnt[r]) + 1) * (__ldg(&g_cnt[c]) + 1);
    g_ecoef[pos] = rsqrtf((float)prod);
}

// ---------------- GEMM: tmp = in@W ; agg = tmp/(cnt+1) (self-loop init) ------
#define KC 32
__global__ void __launch_bounds__(256) k_gemm(
    const float* __restrict__ in, int ldin, int K, const float* __restrict__ W)
{
    __shared__ float sX[256 * 33];
    __shared__ float sW[KC * HH];

    int tid = threadIdx.x;
    int tx = tid & 7;
    int ty = tid >> 3;
    int rowBase = blockIdx.x * 256;
    int c0 = tx * 8;
    int r0 = ty * 8;

    float acc[8][8];
#pragma unroll
    for (int r = 0; r < 8; r++)
#pragma unroll
        for (int c = 0; c < 8; c++) acc[r][c] = 0.0f;

    for (int kc = 0; kc < K; kc += KC) {
        {
            const float4* wsrc = (const float4*)(W + kc * HH);
#pragma unroll
            for (int i = 0; i < 2; i++) {
                int idx = tid + i * 256;
                ((float4*)sW)[idx] = wsrc[idx];
            }
        }
        {
            int k4 = tid & 7;
            int rr = tid >> 3;
#pragma unroll
            for (int p = 0; p < 8; p++) {
                int row = rr + p * 32;
                float4 v = __ldcs((const float4*)(in + (size_t)(rowBase + row) * ldin + kc + k4 * 4));
                float* d = &sX[row * 33 + k4 * 4];
                d[0] = v.x; d[1] = v.y; d[2] = v.z; d[3] = v.w;
            }
        }
        __syncthreads();

#pragma unroll 4
        for (int k = 0; k < KC; k++) {
            float4 w0 = *(const float4*)&sW[k * HH + c0];
            float4 w1 = *(const float4*)&sW[k * HH + c0 + 4];
            float xv[8];
#pragma unroll
            for (int r = 0; r < 8; r++) xv[r] = sX[(r0 + r) * 33 + k];
#pragma unroll
            for (int r = 0; r < 8; r++) {
                acc[r][0] += xv[r] * w0.x; acc[r][1] += xv[r] * w0.y;
                acc[r][2] += xv[r] * w0.z; acc[r][3] += xv[r] * w0.w;
                acc[r][4] += xv[r] * w1.x; acc[r][5] += xv[r] * w1.y;
                acc[r][6] += xv[r] * w1.z; acc[r][7] += xv[r] * w1.w;
            }
        }
        __syncthreads();
    }
#pragma unroll
    for (int r = 0; r < 8; r++) {
        int row = rowBase + r0 + r;
        float sc = 1.0f / (float)(__ldg(&g_cnt[row]) + 1);   // dinv^2 exactly
        float* o = &g_tmp[(size_t)row * HH + c0];
        *(float4*)o       = make_float4(acc[r][0], acc[r][1], acc[r][2], acc[r][3]);
        *(float4*)(o + 4) = make_float4(acc[r][4], acc[r][5], acc[r][6], acc[r][7]);
        float* a = &g_agg[(size_t)row * HH + c0];
        *(float4*)a       = make_float4(acc[r][0]*sc, acc[r][1]*sc, acc[r][2]*sc, acc[r][3]*sc);
        *(float4*)(a + 4) = make_float4(acc[r][4]*sc, acc[r][5]*sc, acc[r][6]*sc, acc[r][7]*sc);
    }
}

// ---------------- scatter: 8 dst-sorted CSR slots/thread, pre-summed REDs ----
__device__ __forceinline__ void red4(float* dst, float4 v) {
    asm volatile("red.global.add.v4.f32 [%0], {%1, %2, %3, %4};"
                 :: "l"(dst), "f"(v.x), "f"(v.y), "f"(v.z), "f"(v.w)
                 : "memory");
}
__global__ void __launch_bounds__(256) k_scatter() {
    int t = blockIdx.x * 256 + threadIdx.x;   // t < (EE/8)*16
    int q = t >> 4;
    int g = t & 15;
    int base = q * 8;

    int2 ed[8];
#pragma unroll
    for (int i = 0; i < 4; i++) {
        int4 p = __ldg((const int4*)&g_es[base + i * 2]);
        ed[i * 2 + 0] = make_int2(p.x, p.y);
        ed[i * 2 + 1] = make_int2(p.z, p.w);
    }
    float cf[8];
    {
        float4 a = __ldg((const float4*)&g_ecoef[base]);
        float4 b = __ldg((const float4*)&g_ecoef[base + 4]);
        cf[0] = a.x; cf[1] = a.y; cf[2] = a.z; cf[3] = a.w;
        cf[4] = b.x; cf[5] = b.y; cf[6] = b.z; cf[7] = b.w;
    }

    const float4* tp = (const float4*)g_tmp;   // 16 float4 per node row
    float4 v[8];
#pragma unroll
    for (int i = 0; i < 8; i++) v[i] = tp[(size_t)ed[i].x * 16 + g];
#pragma unroll
    for (int i = 0; i < 8; i++) {
        v[i].x *= cf[i]; v[i].y *= cf[i]; v[i].z *= cf[i]; v[i].w *= cf[i];
    }

    float4 s = v[0]; int d = ed[0].y;
#pragma unroll
    for (int i = 1; i < 8; i++) {
        if (ed[i].y == d) {
            s.x += v[i].x; s.y += v[i].y; s.z += v[i].z; s.w += v[i].w;
        } else {
            red4(&g_agg[(size_t)d * HH + g * 4], s);
            s = v[i]; d = ed[i].y;
        }
    }
    red4(&g_agg[(size_t)d * HH + g * 4], s);
}

// ---------------- finalize: bias + tanh (+rowmax) ----------------------------
__global__ void __launch_bounds__(256) k_finalize(
    const float* __restrict__ b, int off, int do_rowmax)
{
    int warp = (blockIdx.x * blockDim.x + threadIdx.x) >> 5;
    int lane = threadIdx.x & 31;
    if (warp >= NN) return;
    int n = warp;

    const float2* agg2 = (const float2*)g_agg;
    float2 acc = agg2[(size_t)n * 32 + lane];

    int c = lane * 2;
    float y0 = tanhf(acc.x + b[c]);          // exact tanh: sort keys
    float y1 = tanhf(acc.y + b[c + 1]);
    ((float2*)&g_feat[(size_t)n * FEATW + off])[lane] = make_float2(y0, y1);

    if (do_rowmax) {
        const float2* f2 = (const float2*)&g_feat[(size_t)n * FEATW];
        float2 p = f2[lane];
        float2 q = f2[32 + lane];
        float m = fmaxf(fmaxf(y0, y1), fmaxf(fmaxf(p.x, p.y), fmaxf(q.x, q.y)));
#pragma unroll
        for (int o = 16; o; o >>= 1) m = fmaxf(m, __shfl_xor_sync(0xffffffffu, m, o));
        if (lane == 0) g_rowmax[n] = m;
    }
}

// ---------------- fused tail: select + sort + CNN head, block per graph ------
// 320 threads = 10 warps. Warp 0 selects top-10 nodes; warp w sorts row w;
// sorted rows (ascending, FLT_MAX-padded) ARE the pooled tensor; conv head
// then runs entirely from shared.
__global__ void __launch_bounds__(320) k_tail(
    const float* __restrict__ Wc1, const float* __restrict__ bc1,
    const float* __restrict__ Wc2, const float* __restrict__ bc2,
    const float* __restrict__ Wf,  const float* __restrict__ bf,
    float* c_out, float* xf_out)
{
    __shared__ float s_sort[KK][256];     // sorted rows; [k][0..191] = pooled
    __shared__ int   s_sel[KK];
    __shared__ float s_w1[32 * KK * 4];
    __shared__ float s_w2[64 * 32 * 3];
    __shared__ float s_a[32 * 48];
    __shared__ float s_b[32 * 12];
    __shared__ float s_y[64 * 4];
    __shared__ float s_xf[64];

    int gph = blockIdx.x;
    int tid = threadIdx.x;
    int warp = tid >> 5, lane = tid & 31;

    // weight staging (all warps help)
    for (int i = tid; i < 32 * KK * 4; i += 320) s_w1[i] = Wc1[i];
    for (int i = tid; i < 64 * 32 * 3; i += 320) s_w2[i] = Wc2[i];

    // ---- select top-KK (warp 0), stable: value desc, index asc ----
    if (warp == 0) {
        const float* rm = &g_rowmax[gph * 50];
        float v0 = (lane < 50) ? rm[lane] : -FLT_MAX;
        float v1 = (lane + 32 < 50) ? rm[lane + 32] : -FLT_MAX;
        bool u0 = false, u1 = false;
#pragma unroll 1
        for (int k = 0; k < KK; k++) {
            float c = -FLT_MAX; int ci = 1 << 20;
            if (!u0) { c = v0; ci = lane; }
            if (!u1 && (v1 > c || (v1 == c && lane + 32 < ci))) { c = v1; ci = lane + 32; }
#pragma unroll
            for (int o = 16; o; o >>= 1) {
                float oc = __shfl_xor_sync(0xffffffffu, c, o);
                int   oi = __shfl_xor_sync(0xffffffffu, ci, o);
                if (oc > c || (oc == c && oi < ci)) { c = oc; ci = oi; }
            }
            if (ci == lane) u0 = true;
            else if (ci == lane + 32) u1 = true;
            if (lane == 0) s_sel[k] = gph * 50 + ci;
        }
    }
    __syncthreads();

    // ---- each warp sorts its selected row (256-wide bitonic, +inf pad) ----
    {
        int node = s_sel[warp];
        const float* f = &g_feat[(size_t)node * FEATW];
        for (int i = lane; i < FEATW; i += 32) s_sort[warp][i] = f[i];
        for (int i = FEATW + lane; i < 256; i += 32) s_sort[warp][i] = FLT_MAX;
        __syncwarp();
        for (int k = 2; k <= 256; k <<= 1) {
            for (int j = k >> 1; j > 0; j >>= 1) {
                for (int i = lane; i < 256; i += 32) {
                    int ixj = i ^ j;
                    if (ixj > i) {
                        bool up = ((i & k) == 0);
                        float a = s_sort[warp][i], bb = s_sort[warp][ixj];
                        if ((a > bb) == up) { s_sort[warp][i] = bb; s_sort[warp][ixj] = a; }
                    }
                }
                __syncwarp();
            }
        }
    }
    __syncthreads();

    // ---- conv1: [10,192] -> [32,48] relu ----
    for (int idx = tid; idx < 32 * 48; idx += 320) {
        int oc = idx / 48, t = idx % 48;
        float acc = bc1[oc];
#pragma unroll
        for (int ic = 0; ic < KK; ic++) {
            const float* pp = &s_sort[ic][t * 4];
            const float* ww = &s_w1[oc * (KK * 4) + ic * 4];
            acc += pp[0]*ww[0] + pp[1]*ww[1] + pp[2]*ww[2] + pp[3]*ww[3];
        }
        s_a[idx] = fmaxf(acc, 0.0f);
    }
    __syncthreads();
    for (int idx = tid; idx < 32 * 12; idx += 320) {
        int oc = idx / 12, t = idx % 12;
        const float* a = &s_a[oc * 48 + t * 4];
        s_b[idx] = fmaxf(fmaxf(a[0], a[1]), fmaxf(a[2], a[3]));
    }
    __syncthreads();
    for (int idx = tid; idx < 64 * 4; idx += 320) {
        int oc = idx / 4, t = idx % 4;
        float acc = bc2[oc];
#pragma unroll
        for (int ic = 0; ic < 32; ic++) {
            const float* bb = &s_b[ic * 12 + t * 3];
            const float* ww = &s_w2[oc * 96 + ic * 3];
            acc += bb[0]*ww[0] + bb[1]*ww[1] + bb[2]*ww[2];
        }
        s_y[idx] = fmaxf(acc, 0.0f);
    }
    __syncthreads();
    if (tid < 64) {
        const float* y = &s_y[tid * 4];
        float v = fmaxf(fmaxf(y[0], y[1]), fmaxf(y[2], y[3]));
        s_xf[tid] = v;
        if (xf_out) xf_out[(size_t)gph * 64 + tid] = v;
    }
    __syncthreads();
    if (tid < 10 && c_out) {
        float acc = bf[tid];
#pragma unroll
        for (int i = 0; i < 64; i++) acc += fmaxf(s_xf[i], 0.0f) * Wf[i * 10 + tid];
        c_out[(size_t)gph * 10 + tid] = acc;
    }
}

// ---------------- launcher ----------------------------------------------------
extern "C" void kernel_launch(void* const* d_in, const int* in_sizes, int n_in,
                              void* d_out, int out_size)
{
    const float* x   = (const float*)d_in[0];
    const int*   ei  = (const int*)  d_in[1];
    const float* W1  = (const float*)d_in[3];
    const float* b1  = (const float*)d_in[4];
    const float* W2  = (const float*)d_in[5];
    const float* b2  = (const float*)d_in[6];
    const float* W3  = (const float*)d_in[7];
    const float* b3  = (const float*)d_in[8];
    const float* Wc1 = (const float*)d_in[9];
    const float* bc1 = (const float*)d_in[10];
    const float* Wc2 = (const float*)d_in[11];
    const float* bc2 = (const float*)d_in[12];
    const float* Wf  = (const float*)d_in[13];
    const float* bf  = (const float*)d_in[14];

    float* out = (float*)d_out;
    float* c_out  = nullptr;
    float* xf_out = nullptr;
    if (out_size >= BB * 74) { c_out = out; xf_out = out + BB * 10; }
    else if (out_size == BB * 10) { c_out = out; }
    else { xf_out = out; }

    const int GB = NN / 256;              // gemm blocks (800)
    const int SB = (EE * 2) / 256;        // scatter blocks (12800)
    const int FB = (NN * 32) / 256;       // finalize blocks (warp/node)

    float* featp = nullptr;
    cudaGetSymbolAddress((void**)&featp, g_feat);
    void* p_cnt = nullptr;
    cudaGetSymbolAddress(&p_cnt, g_cnt);
    cudaMemsetAsync(p_cnt, 0, NN * sizeof(int));     // graph node

    k_count   <<<EE / 256, 256>>>(ei);               // k1
    k_gemm    <<<GB, 256>>>(x, FIN, FIN, W1);        // k2 (needs cnt only)
    k_scan1   <<<800, 256>>>();                      // k3
    k_scan2   <<<1, 1024>>>();                       // k4
    k_scan3   <<<800, 256>>>();                      // k5
    k_fill    <<<EE / 256, 256>>>(ei);               // k6

    k_scatter <<<SB, 256>>>();                       // k7
    k_finalize<<<FB, 256>>>(b1, 0, 0);               // k8

    k_gemm    <<<GB, 256>>>(featp + 0, FEATW, HH, W2);   // k9
    k_scatter <<<SB, 256>>>();                       // k10
    k_finalize<<<FB, 256>>>(b2, 64, 0);              // k11

    k_gemm    <<<GB, 256>>>(featp + 64, FEATW, HH, W3);  // k12
    k_scatter <<<SB, 256>>>();                       // k13
    k_finalize<<<FB, 256>>>(b3, 128, 1);             // k14

    k_tail<<<BB, 320>>>(Wc1, bc1, Wc2, bc2, Wf, bf, c_out, xf_out); // k15
}